// round 2
// baseline (speedup 1.0000x reference)
#include <cuda_runtime.h>
#include <cuda_bf16.h>
#include <cstdint>

// ---------------------------------------------------------------------------
// DrugEmbed: GCNConv(128->128) -> BN -> ReLU -> GCNConv(128->100) -> seg-max
//
// Decomposition (norm folded):
//   h'  = (X @ W) * dinv[row]                      (GEMM epilogue prescale)
//   agg[d] = h'[d] + sum_{e: dst=d} h'[src_e]      (self-loop = init value)
//   out[d] = agg[d] * dinv[d] + b
// ---------------------------------------------------------------------------

#define NMAX 200000
#define DH   128

__device__ __align__(16) float g_bufA[(size_t)NMAX * DH];
__device__ __align__(16) float g_bufB[(size_t)NMAX * DH];
__device__ float g_deg[NMAX];
__device__ float g_dinv[NMAX];
__device__ float g_bnsum[DH];
__device__ float g_bnsumsq[DH];
__device__ float g_bnscale[DH];
__device__ float g_bnshift[DH];

// ---------------------------------------------------------------------------
// init: deg=1 (self loop), BN accumulators=0, output=-inf
// ---------------------------------------------------------------------------
__global__ void init_kernel(unsigned int* out, int out_n, int nrows) {
    int i = blockIdx.x * blockDim.x + threadIdx.x;
    if (i < nrows) g_deg[i] = 1.0f;
    if (i < out_n) out[i] = 0xFF800000u;  // -inf bits
    if (i < DH) { g_bnsum[i] = 0.0f; g_bnsumsq[i] = 0.0f; }
}

__global__ void deg_kernel(const int* __restrict__ dst, int E) {
    int e = blockIdx.x * blockDim.x + threadIdx.x;
    if (e < E) atomicAdd(&g_deg[dst[e]], 1.0f);
}

__global__ void dinv_kernel(int nrows) {
    int i = blockIdx.x * blockDim.x + threadIdx.x;
    if (i < nrows) g_dinv[i] = rsqrtf(g_deg[i]);  // deg >= 1 always (self loop)
}

// ---------------------------------------------------------------------------
// Tiled fp32 GEMM: C[nrows, NCOLS] = A[nrows,128] @ W[128,NCOLS]
//   - optional BN+ReLU applied to A elements on load (for layer 2)
//   - epilogue scales rows by dinv and writes BOTH the gather buffer and the
//     aggregation accumulator (self-loop init), stride 128 each.
//   - A_INTERNAL=true reads g_bufA and may write outAcc in-place over its own
//     rows (all A reads complete before the epilogue within a block; blocks
//     own disjoint rows).
// Block: 256 threads, tile 64 rows x 128 cols, thread = 4 rows x 8 cols.
// ---------------------------------------------------------------------------
template<int NCOLS, bool APPLY_BN, bool A_INTERNAL>
__global__ void __launch_bounds__(256)
gemm_kernel(const float* Aext, const float* __restrict__ W, int nrows)
{
    __shared__ float As[16][64];    // [k][row]
    __shared__ float Ws[16][128];   // [k][col]

    const float* A   = A_INTERNAL ? g_bufA : Aext;
    float* outG      = A_INTERNAL ? g_bufB : g_bufA;
    float* outAcc    = A_INTERNAL ? g_bufA : g_bufB;

    const int tid  = threadIdx.x;
    const int tx   = tid & 15;      // col group: cols tx*8 .. tx*8+7
    const int ty   = tid >> 4;      // row group: rows ty*4 .. ty*4+3
    const int row0 = blockIdx.x * 64;

    float acc[4][8];
    #pragma unroll
    for (int r = 0; r < 4; ++r)
        #pragma unroll
        for (int j = 0; j < 8; ++j) acc[r][j] = 0.0f;

    const int la_row = tid >> 2;         // 0..63
    const int la_k   = (tid & 3) << 2;   // 0,4,8,12

    for (int k0 = 0; k0 < 128; k0 += 16) {
        // --- load A chunk (64 x 16), one float4 per thread ---
        {
            int grow = row0 + la_row;
            float4 v = make_float4(0.f, 0.f, 0.f, 0.f);
            if (grow < nrows)
                v = *reinterpret_cast<const float4*>(&A[(size_t)grow * 128 + k0 + la_k]);
            if (APPLY_BN) {
                int k = k0 + la_k;
                v.x = fmaxf(fmaf(v.x, g_bnscale[k + 0], g_bnshift[k + 0]), 0.f);
                v.y = fmaxf(fmaf(v.y, g_bnscale[k + 1], g_bnshift[k + 1]), 0.f);
                v.z = fmaxf(fmaf(v.z, g_bnscale[k + 2], g_bnshift[k + 2]), 0.f);
                v.w = fmaxf(fmaf(v.w, g_bnscale[k + 3], g_bnshift[k + 3]), 0.f);
            }
            As[la_k + 0][la_row] = v.x;
            As[la_k + 1][la_row] = v.y;
            As[la_k + 2][la_row] = v.z;
            As[la_k + 3][la_row] = v.w;
        }
        // --- load W chunk (16 x 128), zero-padding cols >= NCOLS ---
        #pragma unroll
        for (int p = 0; p < 2; ++p) {
            int idx = tid + p * 256;
            int kk  = idx >> 5;
            int c   = (idx & 31) << 2;
            float4 v;
            if (NCOLS == 128) {
                v = *reinterpret_cast<const float4*>(&W[(size_t)(k0 + kk) * 128 + c]);
            } else {
                if (c + 4 <= NCOLS) {
                    v = *reinterpret_cast<const float4*>(&W[(size_t)(k0 + kk) * NCOLS + c]);
                } else {
                    v.x = (c + 0 < NCOLS) ? W[(size_t)(k0 + kk) * NCOLS + c + 0] : 0.f;
                    v.y = (c + 1 < NCOLS) ? W[(size_t)(k0 + kk) * NCOLS + c + 1] : 0.f;
                    v.z = (c + 2 < NCOLS) ? W[(size_t)(k0 + kk) * NCOLS + c + 2] : 0.f;
                    v.w = (c + 3 < NCOLS) ? W[(size_t)(k0 + kk) * NCOLS + c + 3] : 0.f;
                }
            }
            *reinterpret_cast<float4*>(&Ws[kk][c]) = v;
        }
        __syncthreads();

        #pragma unroll
        for (int kk = 0; kk < 16; ++kk) {
            float a[4];
            #pragma unroll
            for (int r = 0; r < 4; ++r) a[r] = As[kk][(ty << 2) + r];
            float4 w0 = *reinterpret_cast<const float4*>(&Ws[kk][tx * 8]);
            float4 w1 = *reinterpret_cast<const float4*>(&Ws[kk][tx * 8 + 4]);
            float w[8] = {w0.x, w0.y, w0.z, w0.w, w1.x, w1.y, w1.z, w1.w};
            #pragma unroll
            for (int r = 0; r < 4; ++r)
                #pragma unroll
                for (int j = 0; j < 8; ++j)
                    acc[r][j] = fmaf(a[r], w[j], acc[r][j]);
        }
        __syncthreads();
    }

    // --- epilogue: scale by dinv[row], write gather buf + accumulator init ---
    #pragma unroll
    for (int r = 0; r < 4; ++r) {
        int grow = row0 + (ty << 2) + r;
        if (grow >= nrows) continue;
        float s = g_dinv[grow];
        #pragma unroll
        for (int j = 0; j < 8; j += 4) {
            int c = tx * 8 + j;
            if (NCOLS < 128 && c >= NCOLS) continue;
            float4 o = make_float4(acc[r][j + 0] * s, acc[r][j + 1] * s,
                                   acc[r][j + 2] * s, acc[r][j + 3] * s);
            *reinterpret_cast<float4*>(&outG  [(size_t)grow * 128 + c]) = o;
            *reinterpret_cast<float4*>(&outAcc[(size_t)grow * 128 + c]) = o;
        }
    }
}

// ---------------------------------------------------------------------------
// Edge aggregation: one warp per edge; accum[dst] += gather[src] via
// vectorized global reductions (red.global.add.v4.f32).
// NV4 = number of float4 lanes (32 for 128 feats, 25 for 100 feats).
// ---------------------------------------------------------------------------
template<int NV4, bool SWAP>
__global__ void __launch_bounds__(256)
edge_agg_kernel(const int* __restrict__ src, const int* __restrict__ dst, int E)
{
    const float* gather = SWAP ? g_bufB : g_bufA;
    float* accum        = SWAP ? g_bufA : g_bufB;

    int gw   = (blockIdx.x * blockDim.x + threadIdx.x) >> 5;
    int lane = threadIdx.x & 31;
    if (gw >= E) return;
    int s = src[gw];
    int d = dst[gw];
    if (lane < NV4) {
        float4 v = *reinterpret_cast<const float4*>(&gather[(size_t)s * 128 + lane * 4]);
        float* p = &accum[(size_t)d * 128 + lane * 4];
        asm volatile("red.global.add.v4.f32 [%0], {%1,%2,%3,%4};"
                     :: "l"(p), "f"(v.x), "f"(v.y), "f"(v.z), "f"(v.w)
                     : "memory");
    }
}

// ---------------------------------------------------------------------------
// finalize layer 1: x1 = agg*dinv + b1 (write to bufA), accumulate BN stats.
// Block = 64 rows, threads (128 cols x 2 row-halves).
// ---------------------------------------------------------------------------
__global__ void __launch_bounds__(256)
finalize1_kernel(const float* __restrict__ b1, int nrows)
{
    __shared__ float ssum[256];
    __shared__ float ssq[256];
    int c    = threadIdx.x & 127;
    int half = threadIdx.x >> 7;
    int row0 = blockIdx.x * 64;
    float bias = b1[c];
    float s = 0.f, q = 0.f;
    for (int r = half; r < 64; r += 2) {
        int row = row0 + r;
        if (row >= nrows) break;
        float v = g_bufB[(size_t)row * 128 + c] * g_dinv[row] + bias;
        g_bufA[(size_t)row * 128 + c] = v;
        s += v;
        q += v * v;
    }
    ssum[threadIdx.x] = s;
    ssq[threadIdx.x]  = q;
    __syncthreads();
    if (half == 0) {
        atomicAdd(&g_bnsum[c],   ssum[c] + ssum[c + 128]);
        atomicAdd(&g_bnsumsq[c], ssq[c]  + ssq[c + 128]);
    }
}

__global__ void bn_params_kernel(const float* __restrict__ gamma,
                                 const float* __restrict__ beta, float inv_n)
{
    int c = threadIdx.x;
    float mean = g_bnsum[c] * inv_n;
    float var  = fmaxf(g_bnsumsq[c] * inv_n - mean * mean, 0.0f);
    float sc   = gamma[c] * rsqrtf(var + 1e-5f);
    g_bnscale[c] = sc;
    g_bnshift[c] = beta[c] - mean * sc;
}

// ---------------------------------------------------------------------------
// finalize layer 2 + global max pool: x2 = agg*dinv + b2; atomicMax into out.
// ---------------------------------------------------------------------------
__device__ __forceinline__ void atomicMaxF(float* addr, float v) {
    if (v >= 0.0f) atomicMax(reinterpret_cast<int*>(addr), __float_as_int(v));
    else           atomicMin(reinterpret_cast<unsigned int*>(addr), __float_as_uint(v));
}

__global__ void __launch_bounds__(256)
pool_kernel(const float* __restrict__ b2, const int* __restrict__ batch,
            float* out, int nrows)
{
    int idx = blockIdx.x * blockDim.x + threadIdx.x;
    if (idx >= nrows * 100) return;
    int row = idx / 100;
    int c   = idx - row * 100;
    float v = g_bufA[(size_t)row * 128 + c] * g_dinv[row] + b2[c];
    atomicMaxF(&out[(size_t)batch[row] * 100 + c], v);
}

// ---------------------------------------------------------------------------
extern "C" void kernel_launch(void* const* d_in, const int* in_sizes, int n_in,
                              void* d_out, int out_size)
{
    const float* atom  = (const float*)d_in[0];   // [N,128]
    const int*   eidx  = (const int*)d_in[1];     // [2,E]
    const int*   batch = (const int*)d_in[2];     // [N]

    // num_graphs may appear as a size-1 int input at index 3
    int base = 3;
    if (n_in >= 10 && in_sizes[3] == 1) base = 4;
    const float* W1    = (const float*)d_in[base + 0];
    const float* b1    = (const float*)d_in[base + 1];
    const float* gamma = (const float*)d_in[base + 2];
    const float* beta  = (const float*)d_in[base + 3];
    const float* W2    = (const float*)d_in[base + 4];
    const float* b2    = (const float*)d_in[base + 5];

    const int N = in_sizes[2];
    const int E = in_sizes[1] / 2;
    const int* src = eidx;
    const int* dst = eidx + E;
    float* out = (float*)d_out;

    const int initN = (N > out_size) ? N : out_size;
    init_kernel<<<(initN + 255) / 256, 256>>>((unsigned int*)d_out, out_size, N);
    deg_kernel<<<(E + 255) / 256, 256>>>(dst, E);
    dinv_kernel<<<(N + 255) / 256, 256>>>(N);

    const int gblocks = (N + 63) / 64;
    const int eblocks = (E + 7) / 8;

    // Layer 1: h' = (X@W1)*dinv -> bufA (gather) + bufB (accum init = self loop)
    gemm_kernel<128, false, false><<<gblocks, 256>>>(atom, W1, N);
    edge_agg_kernel<32, false><<<eblocks, 256>>>(src, dst, E);
    finalize1_kernel<<<gblocks, 256>>>(b1, N);
    bn_params_kernel<<<1, 128>>>(gamma, beta, 1.0f / (float)N);

    // Layer 2: A = BN+ReLU(x1) on the fly; h2' -> bufB (gather), bufA (accum init)
    gemm_kernel<100, true, true><<<gblocks, 256>>>(nullptr, W2, N);
    edge_agg_kernel<25, true><<<eblocks, 256>>>(src, dst, E);
    pool_kernel<<<((size_t)N * 100 + 255) / 256, 256>>>(b2, batch, out, N);
}

// round 3
// speedup vs baseline: 1.2301x; 1.2301x over previous
#include <cuda_runtime.h>
#include <cuda_bf16.h>
#include <cstdint>

// ---------------------------------------------------------------------------
// DrugEmbed: GCNConv(128->128) -> BN -> ReLU -> GCNConv(128->100) -> seg-max
//
// Decomposition (norm folded):
//   h'  = (X @ W) * dinv[row]                      (GEMM epilogue prescale)
//   agg[d] = h'[d] + sum_{e: dst=d} h'[src_e]      (self-loop = init value)
//   out[d] = agg[d] * dinv[d] + b
//
// R3: GEMM rewritten as 128x128 tile, 8x8 per-thread register blocking,
//     double-buffered smem with register prefetch, and packed fma.rn.f32x2
//     (Blackwell dual-issue fp32 FMA) in the inner loop.
// ---------------------------------------------------------------------------

#define NMAX 200000
#define DH   128

__device__ __align__(16) float g_bufA[(size_t)NMAX * DH];
__device__ __align__(16) float g_bufB[(size_t)NMAX * DH];
__device__ float g_deg[NMAX];
__device__ float g_dinv[NMAX];
__device__ float g_bnsum[DH];
__device__ float g_bnsumsq[DH];
__device__ float g_bnscale[DH];
__device__ float g_bnshift[DH];

// ---------------------------------------------------------------------------
// init: deg=1 (self loop), BN accumulators=0, output=-inf
// ---------------------------------------------------------------------------
__global__ void init_kernel(unsigned int* out, int out_n, int nrows) {
    int i = blockIdx.x * blockDim.x + threadIdx.x;
    if (i < nrows) g_deg[i] = 1.0f;
    if (i < out_n) out[i] = 0xFF800000u;  // -inf bits
    if (i < DH) { g_bnsum[i] = 0.0f; g_bnsumsq[i] = 0.0f; }
}

__global__ void deg_kernel(const int* __restrict__ dst, int E) {
    int e = blockIdx.x * blockDim.x + threadIdx.x;
    if (e < E) atomicAdd(&g_deg[dst[e]], 1.0f);
}

__global__ void dinv_kernel(int nrows) {
    int i = blockIdx.x * blockDim.x + threadIdx.x;
    if (i < nrows) g_dinv[i] = rsqrtf(g_deg[i]);  // deg >= 1 always (self loop)
}

// ---------------------------------------------------------------------------
// GEMM: C[nrows, NCOLS] = A[nrows,128] @ W[128,NCOLS]
// Block: 256 threads, tile 128 rows x 128 cols, thread = 8 rows x 8 cols.
// Inner loop uses packed fma.rn.f32x2 (2 FMAs / instruction).
// Double-buffered smem, k-chunk = 16, register prefetch of next chunk.
// APPLY_BN: BN+ReLU applied to A values in registers during smem staging.
// A_INTERNAL: read g_bufA, write gather->g_bufB, accum-init->g_bufA (in place).
// ---------------------------------------------------------------------------
template<int NCOLS, bool APPLY_BN, bool A_INTERNAL>
__global__ void __launch_bounds__(256, 2)
gemm_kernel(const float* Aext, const float* __restrict__ W, int nrows)
{
    __shared__ float As[2][16][128];   // [buf][k][row]
    __shared__ float Ws[2][16][128];   // [buf][k][col]

    const float* A   = A_INTERNAL ? g_bufA : Aext;
    float* outG      = A_INTERNAL ? g_bufB : g_bufA;
    float* outAcc    = A_INTERNAL ? g_bufA : g_bufB;

    const int tid  = threadIdx.x;
    const int tx   = tid & 15;       // col group: cols tx*8 .. tx*8+7
    const int ty   = tid >> 4;       // row group: rows ty*8 .. ty*8+7
    const int row0 = blockIdx.x * 128;

    // per-thread load coordinates (2 float4 of A, 2 float4 of W per chunk)
    const int a_r0  = tid >> 2;            // A: row within tile (p adds 64)
    const int a_k4  = (tid & 3) << 2;      // A: k offset 0,4,8,12
    const int w_kk0 = tid >> 5;            // W: k row (p adds 8)
    const int w_c4  = (tid & 31) << 2;     // W: col offset

    unsigned long long acc[8][4];          // 8 rows x 4 packed-f32x2 cols
    #pragma unroll
    for (int r = 0; r < 8; ++r)
        #pragma unroll
        for (int j = 0; j < 4; ++j) acc[r][j] = 0ull;

    float4 ra[2], rw[2];

    // ---- load chunk 0 into registers ----
    #pragma unroll
    for (int p = 0; p < 2; ++p) {
        int grow = row0 + a_r0 + p * 64;
        ra[p] = make_float4(0.f, 0.f, 0.f, 0.f);
        if (grow < nrows)
            ra[p] = *reinterpret_cast<const float4*>(&A[(size_t)grow * 128 + a_k4]);
        int kk = w_kk0 + p * 8;
        rw[p] = make_float4(0.f, 0.f, 0.f, 0.f);
        if (NCOLS == 128)
            rw[p] = *reinterpret_cast<const float4*>(&W[(size_t)kk * 128 + w_c4]);
        else if (w_c4 + 4 <= NCOLS)
            rw[p] = *reinterpret_cast<const float4*>(&W[(size_t)kk * NCOLS + w_c4]);
    }

    // ---- stage chunk 0 ----
    #pragma unroll
    for (int p = 0; p < 2; ++p) {
        float4 v = ra[p];
        if (APPLY_BN) {
            int k = a_k4;
            v.x = fmaxf(fmaf(v.x, g_bnscale[k + 0], g_bnshift[k + 0]), 0.f);
            v.y = fmaxf(fmaf(v.y, g_bnscale[k + 1], g_bnshift[k + 1]), 0.f);
            v.z = fmaxf(fmaf(v.z, g_bnscale[k + 2], g_bnshift[k + 2]), 0.f);
            v.w = fmaxf(fmaf(v.w, g_bnscale[k + 3], g_bnshift[k + 3]), 0.f);
        }
        int r = a_r0 + p * 64;
        As[0][a_k4 + 0][r] = v.x;
        As[0][a_k4 + 1][r] = v.y;
        As[0][a_k4 + 2][r] = v.z;
        As[0][a_k4 + 3][r] = v.w;
        *reinterpret_cast<float4*>(&Ws[0][w_kk0 + p * 8][w_c4]) = rw[p];
    }
    __syncthreads();

    int buf = 0;
    #pragma unroll 1
    for (int c = 0; c < 8; ++c) {
        const int k0n = (c + 1) * 16;
        // prefetch next chunk to registers
        if (c < 7) {
            #pragma unroll
            for (int p = 0; p < 2; ++p) {
                int grow = row0 + a_r0 + p * 64;
                ra[p] = make_float4(0.f, 0.f, 0.f, 0.f);
                if (grow < nrows)
                    ra[p] = *reinterpret_cast<const float4*>(&A[(size_t)grow * 128 + k0n + a_k4]);
                int kk = k0n + w_kk0 + p * 8;
                rw[p] = make_float4(0.f, 0.f, 0.f, 0.f);
                if (NCOLS == 128)
                    rw[p] = *reinterpret_cast<const float4*>(&W[(size_t)kk * 128 + w_c4]);
                else if (w_c4 + 4 <= NCOLS)
                    rw[p] = *reinterpret_cast<const float4*>(&W[(size_t)kk * NCOLS + w_c4]);
            }
        }

        // ---- compute on smem[buf] ----
        #pragma unroll
        for (int kk = 0; kk < 16; ++kk) {
            ulonglong2 wlo = *reinterpret_cast<const ulonglong2*>(&Ws[buf][kk][tx * 8]);
            ulonglong2 whi = *reinterpret_cast<const ulonglong2*>(&Ws[buf][kk][tx * 8 + 4]);
            unsigned long long w64[4] = {wlo.x, wlo.y, whi.x, whi.y};
            float4 alo = *reinterpret_cast<const float4*>(&As[buf][kk][ty * 8]);
            float4 ahi = *reinterpret_cast<const float4*>(&As[buf][kk][ty * 8 + 4]);
            float av[8] = {alo.x, alo.y, alo.z, alo.w, ahi.x, ahi.y, ahi.z, ahi.w};
            #pragma unroll
            for (int r = 0; r < 8; ++r) {
                unsigned long long a2;
                asm("mov.b64 %0, {%1, %1};" : "=l"(a2) : "f"(av[r]));
                #pragma unroll
                for (int j = 0; j < 4; ++j) {
                    asm("fma.rn.f32x2 %0, %1, %2, %0;"
                        : "+l"(acc[r][j]) : "l"(a2), "l"(w64[j]));
                }
            }
        }

        // ---- stage prefetched chunk into other buffer ----
        if (c < 7) {
            __syncthreads();
            int nb = buf ^ 1;
            #pragma unroll
            for (int p = 0; p < 2; ++p) {
                float4 v = ra[p];
                if (APPLY_BN) {
                    int k = k0n + a_k4;
                    v.x = fmaxf(fmaf(v.x, g_bnscale[k + 0], g_bnshift[k + 0]), 0.f);
                    v.y = fmaxf(fmaf(v.y, g_bnscale[k + 1], g_bnshift[k + 1]), 0.f);
                    v.z = fmaxf(fmaf(v.z, g_bnscale[k + 2], g_bnshift[k + 2]), 0.f);
                    v.w = fmaxf(fmaf(v.w, g_bnscale[k + 3], g_bnshift[k + 3]), 0.f);
                }
                int r = a_r0 + p * 64;
                As[nb][a_k4 + 0][r] = v.x;
                As[nb][a_k4 + 1][r] = v.y;
                As[nb][a_k4 + 2][r] = v.z;
                As[nb][a_k4 + 3][r] = v.w;
                *reinterpret_cast<float4*>(&Ws[nb][w_kk0 + p * 8][w_c4]) = rw[p];
            }
            __syncthreads();
            buf = nb;
        }
    }

    // ---- epilogue: scale by dinv[row], write gather buf + accumulator init ----
    #pragma unroll
    for (int r = 0; r < 8; ++r) {
        int grow = row0 + ty * 8 + r;
        if (grow >= nrows) continue;
        float s = g_dinv[grow];
        float o[8];
        #pragma unroll
        for (int j = 0; j < 4; ++j) {
            float lo, hi;
            asm("mov.b64 {%0, %1}, %2;" : "=f"(lo), "=f"(hi) : "l"(acc[r][j]));
            o[2 * j]     = lo * s;
            o[2 * j + 1] = hi * s;
        }
        int c0 = tx * 8;
        if (NCOLS == 128 || c0 + 4 <= NCOLS) {
            float4 v = make_float4(o[0], o[1], o[2], o[3]);
            *reinterpret_cast<float4*>(&outG  [(size_t)grow * 128 + c0]) = v;
            *reinterpret_cast<float4*>(&outAcc[(size_t)grow * 128 + c0]) = v;
        }
        if (NCOLS == 128 || c0 + 8 <= NCOLS) {
            float4 v = make_float4(o[4], o[5], o[6], o[7]);
            *reinterpret_cast<float4*>(&outG  [(size_t)grow * 128 + c0 + 4]) = v;
            *reinterpret_cast<float4*>(&outAcc[(size_t)grow * 128 + c0 + 4]) = v;
        }
    }
}

// ---------------------------------------------------------------------------
// Edge aggregation layer 1 (128 feats = 32 float4): one warp per edge.
// ---------------------------------------------------------------------------
__global__ void __launch_bounds__(256)
edge_agg128_kernel(const int* __restrict__ src, const int* __restrict__ dst, int E)
{
    int gw   = (blockIdx.x * blockDim.x + threadIdx.x) >> 5;
    int lane = threadIdx.x & 31;
    if (gw >= E) return;
    int s = __ldg(&src[gw]);
    int d = __ldg(&dst[gw]);
    float4 v = *reinterpret_cast<const float4*>(&g_bufA[(size_t)s * 128 + lane * 4]);
    float* p = &g_bufB[(size_t)d * 128 + lane * 4];
    asm volatile("red.global.add.v4.f32 [%0], {%1,%2,%3,%4};"
                 :: "l"(p), "f"(v.x), "f"(v.y), "f"(v.z), "f"(v.w)
                 : "memory");
}

// ---------------------------------------------------------------------------
// Edge aggregation layer 2 (100 feats = 25 float4): 10 edges per 256-thread
// block, flat lane mapping (250/256 lanes active instead of 25/32).
// ---------------------------------------------------------------------------
__global__ void __launch_bounds__(256)
edge_agg100_kernel(const int* __restrict__ src, const int* __restrict__ dst, int E)
{
    int t = threadIdx.x;
    if (t >= 250) return;
    int el = t / 25;
    int j  = t - el * 25;
    int e  = blockIdx.x * 10 + el;
    if (e >= E) return;
    int s = __ldg(&src[e]);
    int d = __ldg(&dst[e]);
    float4 v = *reinterpret_cast<const float4*>(&g_bufB[(size_t)s * 128 + j * 4]);
    float* p = &g_bufA[(size_t)d * 128 + j * 4];
    asm volatile("red.global.add.v4.f32 [%0], {%1,%2,%3,%4};"
                 :: "l"(p), "f"(v.x), "f"(v.y), "f"(v.z), "f"(v.w)
                 : "memory");
}

// ---------------------------------------------------------------------------
// finalize layer 1: x1 = agg*dinv + b1 (write to bufA), accumulate BN stats.
// ---------------------------------------------------------------------------
__global__ void __launch_bounds__(256)
finalize1_kernel(const float* __restrict__ b1, int nrows)
{
    __shared__ float ssum[256];
    __shared__ float ssq[256];
    int c    = threadIdx.x & 127;
    int half = threadIdx.x >> 7;
    int row0 = blockIdx.x * 64;
    float bias = b1[c];
    float s = 0.f, q = 0.f;
    for (int r = half; r < 64; r += 2) {
        int row = row0 + r;
        if (row >= nrows) break;
        float v = g_bufB[(size_t)row * 128 + c] * g_dinv[row] + bias;
        g_bufA[(size_t)row * 128 + c] = v;
        s += v;
        q += v * v;
    }
    ssum[threadIdx.x] = s;
    ssq[threadIdx.x]  = q;
    __syncthreads();
    if (half == 0) {
        atomicAdd(&g_bnsum[c],   ssum[c] + ssum[c + 128]);
        atomicAdd(&g_bnsumsq[c], ssq[c]  + ssq[c + 128]);
    }
}

__global__ void bn_params_kernel(const float* __restrict__ gamma,
                                 const float* __restrict__ beta, float inv_n)
{
    int c = threadIdx.x;
    float mean = g_bnsum[c] * inv_n;
    float var  = fmaxf(g_bnsumsq[c] * inv_n - mean * mean, 0.0f);
    float sc   = gamma[c] * rsqrtf(var + 1e-5f);
    g_bnscale[c] = sc;
    g_bnshift[c] = beta[c] - mean * sc;
}

// ---------------------------------------------------------------------------
// finalize layer 2 + global max pool: x2 = agg*dinv + b2; atomicMax into out.
// ---------------------------------------------------------------------------
__device__ __forceinline__ void atomicMaxF(float* addr, float v) {
    if (v >= 0.0f) atomicMax(reinterpret_cast<int*>(addr), __float_as_int(v));
    else           atomicMin(reinterpret_cast<unsigned int*>(addr), __float_as_uint(v));
}

__global__ void __launch_bounds__(256)
pool_kernel(const float* __restrict__ b2, const int* __restrict__ batch,
            float* out, int nrows)
{
    int idx = blockIdx.x * blockDim.x + threadIdx.x;
    if (idx >= nrows * 100) return;
    int row = idx / 100;
    int c   = idx - row * 100;
    float v = g_bufA[(size_t)row * 128 + c] * g_dinv[row] + b2[c];
    atomicMaxF(&out[(size_t)batch[row] * 100 + c], v);
}

// ---------------------------------------------------------------------------
extern "C" void kernel_launch(void* const* d_in, const int* in_sizes, int n_in,
                              void* d_out, int out_size)
{
    const float* atom  = (const float*)d_in[0];   // [N,128]
    const int*   eidx  = (const int*)d_in[1];     // [2,E]
    const int*   batch = (const int*)d_in[2];     // [N]

    // num_graphs may appear as a size-1 int input at index 3
    int base = 3;
    if (n_in >= 10 && in_sizes[3] == 1) base = 4;
    const float* W1    = (const float*)d_in[base + 0];
    const float* b1    = (const float*)d_in[base + 1];
    const float* gamma = (const float*)d_in[base + 2];
    const float* beta  = (const float*)d_in[base + 3];
    const float* W2    = (const float*)d_in[base + 4];
    const float* b2    = (const float*)d_in[base + 5];

    const int N = in_sizes[2];
    const int E = in_sizes[1] / 2;
    const int* src = eidx;
    const int* dst = eidx + E;
    float* out = (float*)d_out;

    const int initN = (N > out_size) ? N : out_size;
    init_kernel<<<(initN + 255) / 256, 256>>>((unsigned int*)d_out, out_size, N);
    deg_kernel<<<(E + 255) / 256, 256>>>(dst, E);
    dinv_kernel<<<(N + 255) / 256, 256>>>(N);

    const int gblocks = (N + 127) / 128;

    // Layer 1: h' = (X@W1)*dinv -> bufA (gather) + bufB (accum init = self loop)
    gemm_kernel<128, false, false><<<gblocks, 256>>>(atom, W1, N);
    edge_agg128_kernel<<<(E + 7) / 8, 256>>>(src, dst, E);
    finalize1_kernel<<<(N + 63) / 64, 256>>>(b1, N);
    bn_params_kernel<<<1, 128>>>(gamma, beta, 1.0f / (float)N);

    // Layer 2: A = BN+ReLU(x1) on the fly; h2' -> bufB (gather), bufA (accum init)
    gemm_kernel<100, true, true><<<gblocks, 256>>>(nullptr, W2, N);
    edge_agg100_kernel<<<(E + 9) / 10, 256>>>(src, dst, E);
    pool_kernel<<<((size_t)N * 100 + 255) / 256, 256>>>(b2, batch, out, N);
}

// round 5
// speedup vs baseline: 1.5057x; 1.2241x over previous
#include <cuda_runtime.h>
#include <cuda_bf16.h>
#include <cstdint>

// ---------------------------------------------------------------------------
// DrugEmbed: GCNConv(128->128) -> BN -> ReLU -> GCNConv(128->100) -> seg-max
// R5: GEMMs on mma.sync.m16n8k16 (bf16 hi/lo split, 3-term fp32-accurate).
//     tcgen05 is unavailable (toolchain targets sm_100 plain, not sm_100a).
// ---------------------------------------------------------------------------

#define NMAX 200000
#define DH   128

__device__ __align__(16) float g_bufA[(size_t)NMAX * DH];
__device__ __align__(16) float g_bufB[(size_t)NMAX * DH];
__device__ float g_deg[NMAX];
__device__ float g_dinv[NMAX];
__device__ __align__(16) float g_bnsum[DH];
__device__ __align__(16) float g_bnsumsq[DH];
__device__ __align__(16) float g_bnscale[DH];
__device__ __align__(16) float g_bnshift[DH];

// ------------------------------ helpers -----------------------------------
__device__ __forceinline__ uint32_t smem_u32(const void* p) {
    uint32_t a;
    asm("{ .reg .u64 t; cvta.to.shared.u64 t, %1; cvt.u32.u64 %0, t; }"
        : "=r"(a) : "l"(p));
    return a;
}

__device__ __forceinline__ void ldmx4(uint32_t* r, uint32_t addr) {
    asm volatile("ldmatrix.sync.aligned.m8n8.x4.shared.b16 {%0,%1,%2,%3}, [%4];"
                 : "=r"(r[0]), "=r"(r[1]), "=r"(r[2]), "=r"(r[3]) : "r"(addr));
}
__device__ __forceinline__ void ldmx4t(uint32_t* r, uint32_t addr) {
    asm volatile("ldmatrix.sync.aligned.m8n8.x4.trans.shared.b16 {%0,%1,%2,%3}, [%4];"
                 : "=r"(r[0]), "=r"(r[1]), "=r"(r[2]), "=r"(r[3]) : "r"(addr));
}
__device__ __forceinline__ void mma_bf16(float* d, const uint32_t* a,
                                         uint32_t b0, uint32_t b1) {
    asm volatile(
        "mma.sync.aligned.m16n8k16.row.col.f32.bf16.bf16.f32 "
        "{%0,%1,%2,%3}, {%4,%5,%6,%7}, {%8,%9}, {%0,%1,%2,%3};"
        : "+f"(d[0]), "+f"(d[1]), "+f"(d[2]), "+f"(d[3])
        : "r"(a[0]), "r"(a[1]), "r"(a[2]), "r"(a[3]), "r"(b0), "r"(b1));
}

__device__ __forceinline__ void split8(const float* f, uint4* hiOut, uint4* loOut) {
    __align__(16) __nv_bfloat16 hi8[8], lo8[8];
    #pragma unroll
    for (int j = 0; j < 8; ++j) {
        __nv_bfloat16 h = __float2bfloat16_rn(f[j]);
        hi8[j] = h;
        lo8[j] = __float2bfloat16_rn(f[j] - __bfloat162float(h));
    }
    *hiOut = *reinterpret_cast<const uint4*>(hi8);
    *loOut = *reinterpret_cast<const uint4*>(lo8);
}

// ---------------------------------------------------------------------------
// misc small kernels
// ---------------------------------------------------------------------------
__global__ void init_kernel(unsigned int* out, int out_n, int nrows) {
    int i = blockIdx.x * blockDim.x + threadIdx.x;
    if (i < nrows) g_deg[i] = 1.0f;
    if (i < out_n) out[i] = 0xFF800000u;  // -inf
    if (i < DH) { g_bnsum[i] = 0.0f; g_bnsumsq[i] = 0.0f; }
}
__global__ void deg_kernel(const int* __restrict__ dst, int E) {
    int e = blockIdx.x * blockDim.x + threadIdx.x;
    if (e < E) atomicAdd(&g_deg[dst[e]], 1.0f);
}
__global__ void dinv_kernel(int nrows) {
    int i = blockIdx.x * blockDim.x + threadIdx.x;
    if (i < nrows) g_dinv[i] = rsqrtf(g_deg[i]);
}

// ---------------------------------------------------------------------------
// Tensor-core GEMM tile: C[128, NCOLS] = A[128,128] @ W[128,NCOLS]
// via bf16 split D = Ahi@Whi + Ahi@Wlo + Alo@Whi.
// 256 threads = 8 warps (4m x 2n), warp tile 32x64, mma.m16n8k16.
// Smem: 4 images (Ahi/Alo/Whi/Wlo), 128 rows x 272B (conflict-free ldmatrix).
// Epilogue: dinv row scale -> padded smem transpose -> coalesced dual store.
// ---------------------------------------------------------------------------
template<int NCOLS, bool APPLY_BN, bool A_INTERNAL>
__global__ void __launch_bounds__(256, 1)
gemm_mma_kernel(const float* Aext, const float* __restrict__ W, int nrows)
{
    extern __shared__ char smem[];
    const int LDA = 272;                         // bytes per staged row
    char* AhiP = smem;
    char* AloP = smem + 34816;
    char* WhiP = smem + 69632;
    char* WloP = smem + 104448;
    float* xp  = reinterpret_cast<float*>(smem); // epilogue reuse (67.6KB)

    const int tid  = threadIdx.x;
    const int lane = tid & 31;
    const int wid  = tid >> 5;
    const int row0 = blockIdx.x * 128;

    const float* A = A_INTERNAL ? g_bufA : Aext;
    float* outG    = A_INTERNAL ? g_bufB : g_bufA;
    float* outAcc  = A_INTERNAL ? g_bufA : g_bufB;

    // ---- stage A rows -> bf16 hi/lo (optionally BN+ReLU) ----
    #pragma unroll
    for (int it = 0; it < 8; ++it) {
        int o  = tid + it * 256;
        int m  = o >> 4;
        int k0 = (o & 15) << 3;
        int grow = row0 + m;
        float4 v0 = make_float4(0.f, 0.f, 0.f, 0.f), v1 = v0;
        if (grow < nrows) {
            v0 = *reinterpret_cast<const float4*>(&A[(size_t)grow * 128 + k0]);
            v1 = *reinterpret_cast<const float4*>(&A[(size_t)grow * 128 + k0 + 4]);
        }
        float f[8] = {v0.x, v0.y, v0.z, v0.w, v1.x, v1.y, v1.z, v1.w};
        if (APPLY_BN) {
            float4 s0 = *reinterpret_cast<const float4*>(&g_bnscale[k0]);
            float4 s1 = *reinterpret_cast<const float4*>(&g_bnscale[k0 + 4]);
            float4 t0 = *reinterpret_cast<const float4*>(&g_bnshift[k0]);
            float4 t1 = *reinterpret_cast<const float4*>(&g_bnshift[k0 + 4]);
            float sc[8] = {s0.x, s0.y, s0.z, s0.w, s1.x, s1.y, s1.z, s1.w};
            float sh[8] = {t0.x, t0.y, t0.z, t0.w, t1.x, t1.y, t1.z, t1.w};
            #pragma unroll
            for (int j = 0; j < 8; ++j)
                f[j] = fmaxf(fmaf(f[j], sc[j], sh[j]), 0.f);
        }
        uint4 hi, lo;
        split8(f, &hi, &lo);
        *reinterpret_cast<uint4*>(AhiP + m * LDA + k0 * 2) = hi;
        *reinterpret_cast<uint4*>(AloP + m * LDA + k0 * 2) = lo;
    }

    // ---- stage W (k-major [128][NCOLS]) -> bf16 hi/lo, n padded to 128 ----
    #pragma unroll
    for (int it = 0; it < 8; ++it) {
        int o  = tid + it * 256;
        int k  = o >> 4;
        int n0 = (o & 15) << 3;
        float f[8];
        if (NCOLS == 128) {
            float4 v0 = *reinterpret_cast<const float4*>(&W[(size_t)k * 128 + n0]);
            float4 v1 = *reinterpret_cast<const float4*>(&W[(size_t)k * 128 + n0 + 4]);
            f[0]=v0.x; f[1]=v0.y; f[2]=v0.z; f[3]=v0.w;
            f[4]=v1.x; f[5]=v1.y; f[6]=v1.z; f[7]=v1.w;
        } else {
            #pragma unroll
            for (int j = 0; j < 8; ++j)
                f[j] = (n0 + j < NCOLS) ? W[(size_t)k * NCOLS + n0 + j] : 0.0f;
        }
        uint4 hi, lo;
        split8(f, &hi, &lo);
        *reinterpret_cast<uint4*>(WhiP + k * LDA + n0 * 2) = hi;
        *reinterpret_cast<uint4*>(WloP + k * LDA + n0 * 2) = lo;
    }
    __syncthreads();

    // ---- mma mainloop ----
    const int wm   = (wid & 3) << 5;   // warp row base (0,32,64,96)
    const int wn   = (wid >> 2) << 6;  // warp col base (0,64)
    const int lrow = lane & 15;
    const int lc8  = (lane >> 4) << 3; // 0 or 8

    float acc[2][8][4];
    #pragma unroll
    for (int mt = 0; mt < 2; ++mt)
        #pragma unroll
        for (int nt = 0; nt < 8; ++nt)
            #pragma unroll
            for (int j = 0; j < 4; ++j) acc[mt][nt][j] = 0.0f;

    const uint32_t sAhi = smem_u32(AhiP), sAlo = smem_u32(AloP);
    const uint32_t sWhi = smem_u32(WhiP), sWlo = smem_u32(WloP);
    const int NPAD = (NCOLS + 7) & ~7;

    #pragma unroll
    for (int term = 0; term < 3; ++term) {
        const uint32_t aB = (term == 2) ? sAlo : sAhi;
        const uint32_t bB = (term == 1) ? sWlo : sWhi;
        const uint32_t aAddr0 = aB + (wm + lrow) * LDA + lc8 * 2;
        const uint32_t aAddr1 = aAddr0 + 16 * LDA;
        const uint32_t bAddr  = bB + lrow * LDA + (wn + lc8) * 2;
        #pragma unroll
        for (int ks = 0; ks < 8; ++ks) {
            uint32_t a0[4], a1[4];
            ldmx4(a0, aAddr0 + ks * 32);
            ldmx4(a1, aAddr1 + ks * 32);
            #pragma unroll
            for (int nt2 = 0; nt2 < 4; ++nt2) {
                if (wn + nt2 * 16 >= NPAD) break;
                uint32_t b[4];
                ldmx4t(b, bAddr + ks * 16 * LDA + nt2 * 32);
                mma_bf16(acc[0][2 * nt2 + 0], a0, b[0], b[1]);
                mma_bf16(acc[0][2 * nt2 + 1], a0, b[2], b[3]);
                mma_bf16(acc[1][2 * nt2 + 0], a1, b[0], b[1]);
                mma_bf16(acc[1][2 * nt2 + 1], a1, b[2], b[3]);
            }
        }
    }

    // ---- epilogue: dinv scale -> padded smem (stride 132) ----
    __syncthreads();   // all smem reads done; safe to overwrite with xp
    const int qr = lane >> 2;          // 0..7
    const int qc = (lane & 3) << 1;    // 0,2,4,6
    #pragma unroll
    for (int mt = 0; mt < 2; ++mt) {
        int r_lo = wm + mt * 16 + qr;
        int r_hi = r_lo + 8;
        int g_lo = row0 + r_lo, g_hi = row0 + r_hi;
        float s_lo = (g_lo < nrows) ? g_dinv[g_lo] : 0.0f;
        float s_hi = (g_hi < nrows) ? g_dinv[g_hi] : 0.0f;
        #pragma unroll
        for (int nt = 0; nt < 8; ++nt) {
            int c = wn + nt * 8 + qc;
            float2 vlo = make_float2(acc[mt][nt][0] * s_lo, acc[mt][nt][1] * s_lo);
            float2 vhi = make_float2(acc[mt][nt][2] * s_hi, acc[mt][nt][3] * s_hi);
            *reinterpret_cast<float2*>(&xp[r_lo * 132 + c]) = vlo;
            *reinterpret_cast<float2*>(&xp[r_hi * 132 + c]) = vhi;
        }
    }
    __syncthreads();

    // ---- coalesced dual global stores ----
    #pragma unroll
    for (int it = 0; it < 16; ++it) {
        int i  = tid + it * 256;
        int m  = i >> 5;
        int c4 = (i & 31) << 2;
        int grow = row0 + m;
        if (grow >= nrows) continue;
        if (NCOLS < 128 && c4 >= NCOLS) continue;
        float4 v = *reinterpret_cast<const float4*>(&xp[m * 132 + c4]);
        *reinterpret_cast<float4*>(&outG  [(size_t)grow * 128 + c4]) = v;
        *reinterpret_cast<float4*>(&outAcc[(size_t)grow * 128 + c4]) = v;
    }
}

// ---------------------------------------------------------------------------
// Edge aggregation (unchanged)
// ---------------------------------------------------------------------------
__global__ void __launch_bounds__(256)
edge_agg128_kernel(const int* __restrict__ src, const int* __restrict__ dst, int E)
{
    int gw   = (blockIdx.x * blockDim.x + threadIdx.x) >> 5;
    int lane = threadIdx.x & 31;
    if (gw >= E) return;
    int s = __ldg(&src[gw]);
    int d = __ldg(&dst[gw]);
    float4 v = *reinterpret_cast<const float4*>(&g_bufA[(size_t)s * 128 + lane * 4]);
    float* p = &g_bufB[(size_t)d * 128 + lane * 4];
    asm volatile("red.global.add.v4.f32 [%0], {%1,%2,%3,%4};"
                 :: "l"(p), "f"(v.x), "f"(v.y), "f"(v.z), "f"(v.w) : "memory");
}

__global__ void __launch_bounds__(256)
edge_agg100_kernel(const int* __restrict__ src, const int* __restrict__ dst, int E)
{
    int t = threadIdx.x;
    if (t >= 250) return;
    int el = t / 25;
    int j  = t - el * 25;
    int e  = blockIdx.x * 10 + el;
    if (e >= E) return;
    int s = __ldg(&src[e]);
    int d = __ldg(&dst[e]);
    float4 v = *reinterpret_cast<const float4*>(&g_bufB[(size_t)s * 128 + j * 4]);
    float* p = &g_bufA[(size_t)d * 128 + j * 4];
    asm volatile("red.global.add.v4.f32 [%0], {%1,%2,%3,%4};"
                 :: "l"(p), "f"(v.x), "f"(v.y), "f"(v.z), "f"(v.w) : "memory");
}

// ---------------------------------------------------------------------------
__global__ void __launch_bounds__(256)
finalize1_kernel(const float* __restrict__ b1, int nrows)
{
    __shared__ float ssum[256];
    __shared__ float ssq[256];
    int c    = threadIdx.x & 127;
    int half = threadIdx.x >> 7;
    int row0 = blockIdx.x * 64;
    float bias = b1[c];
    float s = 0.f, q = 0.f;
    for (int r = half; r < 64; r += 2) {
        int row = row0 + r;
        if (row >= nrows) break;
        float v = g_bufB[(size_t)row * 128 + c] * g_dinv[row] + bias;
        g_bufA[(size_t)row * 128 + c] = v;
        s += v;
        q += v * v;
    }
    ssum[threadIdx.x] = s;
    ssq[threadIdx.x]  = q;
    __syncthreads();
    if (half == 0) {
        atomicAdd(&g_bnsum[c],   ssum[c] + ssum[c + 128]);
        atomicAdd(&g_bnsumsq[c], ssq[c]  + ssq[c + 128]);
    }
}

__global__ void bn_params_kernel(const float* __restrict__ gamma,
                                 const float* __restrict__ beta, float inv_n)
{
    int c = threadIdx.x;
    float mean = g_bnsum[c] * inv_n;
    float var  = fmaxf(g_bnsumsq[c] * inv_n - mean * mean, 0.0f);
    float sc   = gamma[c] * rsqrtf(var + 1e-5f);
    g_bnscale[c] = sc;
    g_bnshift[c] = beta[c] - mean * sc;
}

__device__ __forceinline__ void atomicMaxF(float* addr, float v) {
    if (v >= 0.0f) atomicMax(reinterpret_cast<int*>(addr), __float_as_int(v));
    else           atomicMin(reinterpret_cast<unsigned int*>(addr), __float_as_uint(v));
}

__global__ void __launch_bounds__(256)
pool_kernel(const float* __restrict__ b2, const int* __restrict__ batch,
            float* out, int nrows)
{
    int idx = blockIdx.x * blockDim.x + threadIdx.x;
    if (idx >= nrows * 100) return;
    int row = idx / 100;
    int c   = idx - row * 100;
    float v = g_bufA[(size_t)row * 128 + c] * g_dinv[row] + b2[c];
    atomicMaxF(&out[(size_t)batch[row] * 100 + c], v);
}

// ---------------------------------------------------------------------------
extern "C" void kernel_launch(void* const* d_in, const int* in_sizes, int n_in,
                              void* d_out, int out_size)
{
    const float* atom  = (const float*)d_in[0];
    const int*   eidx  = (const int*)d_in[1];
    const int*   batch = (const int*)d_in[2];

    int base = 3;
    if (n_in >= 10 && in_sizes[3] == 1) base = 4;
    const float* W1    = (const float*)d_in[base + 0];
    const float* b1    = (const float*)d_in[base + 1];
    const float* gamma = (const float*)d_in[base + 2];
    const float* beta  = (const float*)d_in[base + 3];
    const float* W2    = (const float*)d_in[base + 4];
    const float* b2    = (const float*)d_in[base + 5];

    const int N = in_sizes[2];
    const int E = in_sizes[1] / 2;
    const int* src = eidx;
    const int* dst = eidx + E;
    float* out = (float*)d_out;

    const int SMEM_BYTES = 139264;  // 4 x 34816
    static bool attr_done = false;
    if (!attr_done) {
        cudaFuncSetAttribute(gemm_mma_kernel<128, false, false>,
                             cudaFuncAttributeMaxDynamicSharedMemorySize, SMEM_BYTES);
        cudaFuncSetAttribute(gemm_mma_kernel<100, true, true>,
                             cudaFuncAttributeMaxDynamicSharedMemorySize, SMEM_BYTES);
        attr_done = true;
    }

    const int initN = (N > out_size) ? N : out_size;
    init_kernel<<<(initN + 255) / 256, 256>>>((unsigned int*)d_out, out_size, N);
    deg_kernel<<<(E + 255) / 256, 256>>>(dst, E);
    dinv_kernel<<<(N + 255) / 256, 256>>>(N);

    const int gblocks = (N + 127) / 128;

    // Layer 1
    gemm_mma_kernel<128, false, false><<<gblocks, 256, SMEM_BYTES>>>(atom, W1, N);
    edge_agg128_kernel<<<(E + 7) / 8, 256>>>(src, dst, E);
    finalize1_kernel<<<(N + 63) / 64, 256>>>(b1, N);
    bn_params_kernel<<<1, 128>>>(gamma, beta, 1.0f / (float)N);

    // Layer 2
    gemm_mma_kernel<100, true, true><<<gblocks, 256, SMEM_BYTES>>>(nullptr, W2, N);
    edge_agg100_kernel<<<(E + 9) / 10, 256>>>(src, dst, E);
    pool_kernel<<<((size_t)N * 100 + 255) / 256, 256>>>(b2, batch, out, N);
}